// round 15
// baseline (speedup 1.0000x reference)
#include <cuda_runtime.h>

// Problem constants (fixed by the reference).
#define BATCH 512
#define LSEQ  24576
#define LP    8192        // LSEQ / 3
#define HID   10

// ---------------------------------------------------------------------------
// Packed f32x2 + MUFU helpers.
// ---------------------------------------------------------------------------
typedef unsigned long long u64;

__device__ __forceinline__ u64 dup2(float x) {
    u64 r;
    asm("mov.b64 %0, {%1, %1};" : "=l"(r) : "f"(x));
    return r;
}
__device__ __forceinline__ u64 pack2(float lo, float hi) {
    u64 r;
    asm("mov.b64 %0, {%1, %2};" : "=l"(r) : "f"(lo), "f"(hi));
    return r;
}
__device__ __forceinline__ u64 ffma2(u64 a, u64 b, u64 c) {
    u64 d;
    asm("fma.rn.f32x2 %0, %1, %2, %3;" : "=l"(d) : "l"(a), "l"(b), "l"(c));
    return d;
}
__device__ __forceinline__ float hsum2(u64 v) {
    float lo, hi;
    asm("mov.b64 {%0, %1}, %2;" : "=f"(lo), "=f"(hi) : "l"(v));
    return lo + hi;
}
__device__ __forceinline__ float tanh_apx(float x) {
    float y;
    asm("tanh.approx.f32 %0, %1;" : "=f"(y) : "f"(x));
    return y;
}

// Shared-memory broadcast helpers.
__device__ __forceinline__ void sts_f32(unsigned addr, float v) {
    asm volatile("st.shared.f32 [%0], %1;" :: "r"(addr), "f"(v) : "memory");
}
__device__ __forceinline__ void lds_v2u64(unsigned addr, u64& a, u64& b) {
    asm volatile("ld.shared.v2.u64 {%0,%1}, [%2];"
                 : "=l"(a), "=l"(b) : "r"(addr) : "memory");
}
__device__ __forceinline__ u64 lds_u64(unsigned addr) {
    u64 a;
    asm volatile("ld.shared.u64 %0, [%1];" : "=l"(a) : "r"(addr) : "memory");
    return a;
}
__device__ __forceinline__ void lds_v2f(unsigned addr, float& a, float& b) {
    asm volatile("ld.shared.v2.f32 {%0,%1}, [%2];"
                 : "=f"(a), "=f"(b) : "r"(addr) : "memory");
}

// ---------------------------------------------------------------------------
// Fused kernel: inline conv1d(k=3,s=3)+relu + LSTM scan + final MLP.
// ONE WARP (32 lanes) per batch element:
//   Half A (lanes 0-15):  lane j owns unit j; chains X=i, Y=g, Z=f;
//                         maintains cst, computes h, stores it to smem.
//   Half B (lanes 16-31): chain X=o (Y,Z slots run don't-care data);
//                         computes og = sig(o), ships it via shfl_xor(16)
//                         (consumed ~28 cyc later -> latency hidden).
// HYBRID h-distribute: h01/h23 via 4 direct SHFLs (first-arrival ~28 cyc,
// beats the STS-commit+LDS ~42), h45/h67/h89 via smem LDS (their chain slots
// come 8-16 cyc later, so the LDS latency overlaps the chain head).
// ---------------------------------------------------------------------------
__global__ void __launch_bounds__(128, 1)
lstm_kernel(const float* __restrict__ x,
            const float* __restrict__ cw,
            const float* __restrict__ cb,
            const float* __restrict__ w_ih,
            const float* __restrict__ w_hh,
            const float* __restrict__ b_ih,
            const float* __restrict__ b_hh,
            const float* __restrict__ mlp_w,
            const float* __restrict__ mlp_b,
            float* __restrict__ out) {
    __shared__ __align__(16) float hbuf[4 * 16];   // 4 warps/block * 16 slots

    int tid  = blockIdx.x * blockDim.x + threadIdx.x;
    int grp  = tid >> 5;                // batch element, 0..511
    int lane = tid & 31;
    int half = lane >> 4;               // 0 = A (i,g,f + cst), 1 = B (o)
    int j    = lane & 15;
    int jc   = j < HID ? j : HID - 1;   // clamp idle lanes onto valid rows
    if (grp >= BATCH) return;

    int seg = (threadIdx.x >> 5);       // warp within block, 0..3
    unsigned sbase = (unsigned)__cvta_generic_to_shared(&hbuf[seg * 16]);
    unsigned smy   = sbase + 4u * (unsigned)j;

    // Conv weights.
    float cw0 = cw[0], cw1 = cw[1], cw2 = cw[2], cb0 = cb[0];

    // Gate rows (torch order i,f,g,o):
    //   chain X: A -> i (row 0), B -> o (row 3); sigmoid, scale 0.5.
    //   chain Y: g (row 2), scale 1   (B's result is don't-care).
    //   chain Z: f (row 1), scale 0.5 (B's result is don't-care).
    int rX = half ? 3 : 0;

    u64 wX2[5], wY2[5], wZ2[5];
#pragma unroll
    for (int p = 0; p < 5; p++) {
        wX2[p] = pack2(0.5f * w_hh[(rX * HID + jc) * HID + 2 * p],
                       0.5f * w_hh[(rX * HID + jc) * HID + 2 * p + 1]);
        wY2[p] = pack2(       w_hh[(2 * HID + jc) * HID + 2 * p],
                              w_hh[(2 * HID + jc) * HID + 2 * p + 1]);
        wZ2[p] = pack2(0.5f * w_hh[(1 * HID + jc) * HID + 2 * p],
                       0.5f * w_hh[(1 * HID + jc) * HID + 2 * p + 1]);
    }
    u64 wxX2 = pack2(0.5f * w_ih[rX * HID + jc], 0.0f);
    u64 wxY2 = pack2(       w_ih[2 * HID + jc], 0.0f);
    u64 wxZ2 = pack2(0.5f * w_ih[1 * HID + jc], 0.0f);
    u64 bbX2 = pack2(0.5f * (b_ih[rX * HID + jc] + b_hh[rX * HID + jc]), 0.0f);
    u64 bbY2 = pack2(       (b_ih[2 * HID + jc] + b_hh[2 * HID + jc]), 0.0f);
    u64 bbZ2 = pack2(0.5f * (b_ih[1 * HID + jc] + b_hh[1 * HID + jc]), 0.0f);

    float cst = 0.0f;
    float hcst = 0.0f;                  // 0.5 * cst (A); don't-care in B
    float h = 0.0f;                     // lane j of A owns h_j
    bool isA = (half == 0);

    // Seed h = 0 in smem (half A owns the slots).
    if (isA) sts_f32(smy, 0.0f);
    __syncwarp();

    const float* xrow = x + (size_t)grp * LSEQ;

    // Load chunk 0 raw (12 floats) and compute its 4 conv outputs.
    float4 A4 = *reinterpret_cast<const float4*>(xrow);
    float4 M4 = *reinterpret_cast<const float4*>(xrow + 4);
    float4 C4 = *reinterpret_cast<const float4*>(xrow + 8);

    float cts[4];
    {
        float o0 = fmaf(A4.x, cw0, fmaf(A4.y, cw1, fmaf(A4.z, cw2, cb0)));
        float o1 = fmaf(A4.w, cw0, fmaf(M4.x, cw1, fmaf(M4.y, cw2, cb0)));
        float o2 = fmaf(M4.z, cw0, fmaf(M4.w, cw1, fmaf(C4.x, cw2, cb0)));
        float o3 = fmaf(C4.y, cw0, fmaf(C4.z, cw1, fmaf(C4.w, cw2, cb0)));
        cts[0] = fmaxf(o0, 0.0f);
        cts[1] = fmaxf(o1, 0.0f);
        cts[2] = fmaxf(o2, 0.0f);
        cts[3] = fmaxf(o3, 0.0f);
    }

    for (int t4 = 0; t4 < LP / 4; t4++) {
        // Prefetch next chunk's raw input (clamped on the last iteration).
        int nidx = t4 + 1 < LP / 4 ? t4 + 1 : t4;
        const float* np = xrow + 12 * nidx;
        A4 = *reinterpret_cast<const float4*>(np);
        M4 = *reinterpret_cast<const float4*>(np + 4);
        C4 = *reinterpret_cast<const float4*>(np + 8);

#pragma unroll
        for (int u = 0; u < 4; u++) {
            u64 ct2 = dup2(cts[u]);     // off critical path (ct known early)

            // Hybrid distribute of previous h:
            //   h01, h23 via 4 SHFLs (fast first-arrival, feeds chain head)
            //   h45, h67, h89 via smem (latency overlapped by chain head)
            float v0 = __shfl_sync(0xffffffffu, h, 0, 32);
            float v1 = __shfl_sync(0xffffffffu, h, 1, 32);
            float v2 = __shfl_sync(0xffffffffu, h, 2, 32);
            float v3 = __shfl_sync(0xffffffffu, h, 3, 32);
            u64 h45, h67, h89;
            lds_v2u64(sbase + 16u, h45, h67);
            h89 = lds_u64(sbase + 32u);
            u64 h01 = pack2(v0, v1);
            u64 h23 = pack2(v2, v3);

            // Seeds (independent of h; scheduled into the distribute shadow).
            u64 aX = ffma2(wxX2, ct2, bbX2);
            u64 aY = ffma2(wxY2, ct2, bbY2);
            u64 aZ = ffma2(wxZ2, ct2, bbZ2);

            // Three 5-deep FFMA2 chains, interleaved.
            aY = ffma2(wY2[0], h01, aY);
            aX = ffma2(wX2[0], h01, aX);
            aZ = ffma2(wZ2[0], h01, aZ);
            aY = ffma2(wY2[1], h23, aY);
            aX = ffma2(wX2[1], h23, aX);
            aZ = ffma2(wZ2[1], h23, aZ);
            aY = ffma2(wY2[2], h45, aY);
            aX = ffma2(wX2[2], h45, aX);
            aZ = ffma2(wZ2[2], h45, aZ);
            aY = ffma2(wY2[3], h67, aY);
            aX = ffma2(wX2[3], h67, aX);
            aZ = ffma2(wZ2[3], h67, aZ);
            aY = ffma2(wY2[4], h89, aY);
            aX = ffma2(wX2[4], h89, aX);
            aZ = ffma2(wZ2[4], h89, aZ);

            // MUFUs in consumption order: tY (hgg first), tX (P), tZ (cst).
            float tY = tanh_apx(hsum2(aY));   // A: tanh(pre_g)
            float tX = tanh_apx(hsum2(aX));   // A: tanh(0.5*pre_i) | B: o
            float tZ = tanh_apx(hsum2(aZ));   // A: tanh(0.5*pre_f)

            // B forms og = sig(o) = 0.5*tX + 0.5; shfl ships it to A
            // (consumed only at the final h-mul -> latency hidden).
            float og_loc = fmaf(tX, 0.5f, 0.5f);
            float og = __shfl_xor_sync(0xffffffffu, og_loc, 16, 32);

            // c-update (valid in A; bounded don't-care in B):
            //   P = 0.5*gg*ti + 0.5*gg ; Q = 0.5*c + P ; c' = fma(0.5*c, tf, Q)
            float hgg = 0.5f * tY;
            float P = fmaf(hgg, tX, hgg);
            float Q = hcst + P;
            cst = fmaf(hcst, tZ, Q);
            hcst = 0.5f * cst;

            h = og * tanh_apx(cst);

            // Publish new h for the next step (half A owns the slots; lanes
            // 4..9 feed the smem reads, 0..3 feed the final MLP).
            if (isA) sts_f32(smy, h);
        }

        // Conv for the prefetched chunk (identical expression order to the
        // reference conv -> bit-identical cts).
        {
            float o0 = fmaf(A4.x, cw0, fmaf(A4.y, cw1, fmaf(A4.z, cw2, cb0)));
            float o1 = fmaf(A4.w, cw0, fmaf(M4.x, cw1, fmaf(M4.y, cw2, cb0)));
            float o2 = fmaf(M4.z, cw0, fmaf(M4.w, cw1, fmaf(C4.x, cw2, cb0)));
            float o3 = fmaf(C4.y, cw0, fmaf(C4.z, cw1, fmaf(C4.w, cw2, cb0)));
            cts[0] = fmaxf(o0, 0.0f);
            cts[1] = fmaxf(o1, 0.0f);
            cts[2] = fmaxf(o2, 0.0f);
            cts[3] = fmaxf(o3, 0.0f);
        }
    }

    // Final MLP: read h_0..h_9 from smem; lanes 0..2 emit the 3 outputs.
    __syncwarp();
    if (lane < 3) {
        float h0, h1, h2, h3, h4, h5, h6, h7, h8, h9;
        lds_v2f(sbase,       h0, h1);
        lds_v2f(sbase + 8u,  h2, h3);
        lds_v2f(sbase + 16u, h4, h5);
        lds_v2f(sbase + 24u, h6, h7);
        lds_v2f(sbase + 32u, h8, h9);
        const float* mw = mlp_w + lane * HID;
        float acc = mlp_b[lane];
        acc = fmaf(mw[0], h0, acc);
        acc = fmaf(mw[1], h1, acc);
        acc = fmaf(mw[2], h2, acc);
        acc = fmaf(mw[3], h3, acc);
        acc = fmaf(mw[4], h4, acc);
        acc = fmaf(mw[5], h5, acc);
        acc = fmaf(mw[6], h6, acc);
        acc = fmaf(mw[7], h7, acc);
        acc = fmaf(mw[8], h8, acc);
        acc = fmaf(mw[9], h9, acc);
        out[grp * 3 + lane] = acc;
    }
}

// ---------------------------------------------------------------------------
extern "C" void kernel_launch(void* const* d_in, const int* in_sizes, int n_in,
                              void* d_out, int out_size) {
    const float* x      = (const float*)d_in[0];
    const float* conv_w = (const float*)d_in[1];
    const float* conv_b = (const float*)d_in[2];
    const float* w_ih   = (const float*)d_in[3];
    const float* w_hh   = (const float*)d_in[4];
    const float* b_ih   = (const float*)d_in[5];
    const float* b_hh   = (const float*)d_in[6];
    const float* mlp_w  = (const float*)d_in[7];
    const float* mlp_b  = (const float*)d_in[8];
    float* out = (float*)d_out;

    // Single fused kernel: 512 batches * 32 lanes = 16384 threads (128 x 128).
    int threads = 128;
    int blocks = (BATCH * 32) / threads;   // 128
    lstm_kernel<<<blocks, threads>>>(x, conv_w, conv_b, w_ih, w_hh,
                                     b_ih, b_hh, mlp_w, mlp_b, out);
}

// round 16
// speedup vs baseline: 1.1296x; 1.1296x over previous
#include <cuda_runtime.h>

// Problem constants (fixed by the reference).
#define BATCH 512
#define LSEQ  24576
#define LP    8192        // LSEQ / 3
#define HID   10

// ---------------------------------------------------------------------------
// Packed f32x2 + MUFU helpers.
// ---------------------------------------------------------------------------
typedef unsigned long long u64;

__device__ __forceinline__ u64 dup2(float x) {
    u64 r;
    asm("mov.b64 %0, {%1, %1};" : "=l"(r) : "f"(x));
    return r;
}
__device__ __forceinline__ u64 pack2(float lo, float hi) {
    u64 r;
    asm("mov.b64 %0, {%1, %2};" : "=l"(r) : "f"(lo), "f"(hi));
    return r;
}
__device__ __forceinline__ u64 ffma2(u64 a, u64 b, u64 c) {
    u64 d;
    asm("fma.rn.f32x2 %0, %1, %2, %3;" : "=l"(d) : "l"(a), "l"(b), "l"(c));
    return d;
}
__device__ __forceinline__ float hsum2(u64 v) {
    float lo, hi;
    asm("mov.b64 {%0, %1}, %2;" : "=f"(lo), "=f"(hi) : "l"(v));
    return lo + hi;
}
__device__ __forceinline__ float tanh_apx(float x) {
    float y;
    asm("tanh.approx.f32 %0, %1;" : "=f"(y) : "f"(x));
    return y;
}

// Shared-memory broadcast helpers: h vector read back as packed 64-bit pairs.
__device__ __forceinline__ void sts_f32(unsigned addr, float v) {
    asm volatile("st.shared.f32 [%0], %1;" :: "r"(addr), "f"(v) : "memory");
}
__device__ __forceinline__ void lds_v2u64(unsigned addr, u64& a, u64& b) {
    asm volatile("ld.shared.v2.u64 {%0,%1}, [%2];"
                 : "=l"(a), "=l"(b) : "r"(addr) : "memory");
}
__device__ __forceinline__ u64 lds_u64(unsigned addr) {
    u64 a;
    asm volatile("ld.shared.u64 %0, [%1];" : "=l"(a) : "r"(addr) : "memory");
    return a;
}
__device__ __forceinline__ void lds_v2f(unsigned addr, float& a, float& b) {
    asm volatile("ld.shared.v2.f32 {%0,%1}, [%2];"
                 : "=f"(a), "=f"(b) : "r"(addr) : "memory");
}

// ---------------------------------------------------------------------------
// Fused kernel: inline conv1d(k=3,s=3)+relu + LSTM scan + final MLP.
// ONE WARP (32 lanes) per batch element:
//   Half A (lanes 0-15):  lane j owns unit j; chains X=i, Y=g, Z=f;
//                         maintains cst, computes h, stores it.
//   Half B (lanes 16-31): chain X=o (Y,Z slots run don't-care data);
//                         computes og = sig(o), ships it via shfl_xor(16)
//                         (consumed ~30+ cyc later -> latency hidden).
// h distribution via smem broadcast (STS + packed-pair LDS) — measured best
// across all variants (pure-shfl and hybrid regressed ~15-18 cyc/step).
// ---------------------------------------------------------------------------
__global__ void __launch_bounds__(128, 1)
lstm_kernel(const float* __restrict__ x,
            const float* __restrict__ cw,
            const float* __restrict__ cb,
            const float* __restrict__ w_ih,
            const float* __restrict__ w_hh,
            const float* __restrict__ b_ih,
            const float* __restrict__ b_hh,
            const float* __restrict__ mlp_w,
            const float* __restrict__ mlp_b,
            float* __restrict__ out) {
    __shared__ __align__(16) float hbuf[4 * 16];   // 4 warps/block * 16 slots

    int tid  = blockIdx.x * blockDim.x + threadIdx.x;
    int grp  = tid >> 5;                // batch element, 0..511
    int lane = tid & 31;
    int half = lane >> 4;               // 0 = A (i,g,f + cst), 1 = B (o)
    int j    = lane & 15;
    int jc   = j < HID ? j : HID - 1;   // clamp idle lanes onto valid rows
    if (grp >= BATCH) return;

    int seg = (threadIdx.x >> 5);       // warp within block, 0..3
    unsigned sbase = (unsigned)__cvta_generic_to_shared(&hbuf[seg * 16]);
    unsigned smy   = sbase + 4u * (unsigned)j;

    // Conv weights.
    float cw0 = cw[0], cw1 = cw[1], cw2 = cw[2], cb0 = cb[0];

    // Gate rows (torch order i,f,g,o):
    //   chain X: A -> i (row 0), B -> o (row 3); sigmoid, scale 0.5.
    //   chain Y: g (row 2), scale 1   (B's result is don't-care).
    //   chain Z: f (row 1), scale 0.5 (B's result is don't-care).
    int rX = half ? 3 : 0;

    u64 wX2[5], wY2[5], wZ2[5];
#pragma unroll
    for (int p = 0; p < 5; p++) {
        wX2[p] = pack2(0.5f * w_hh[(rX * HID + jc) * HID + 2 * p],
                       0.5f * w_hh[(rX * HID + jc) * HID + 2 * p + 1]);
        wY2[p] = pack2(       w_hh[(2 * HID + jc) * HID + 2 * p],
                              w_hh[(2 * HID + jc) * HID + 2 * p + 1]);
        wZ2[p] = pack2(0.5f * w_hh[(1 * HID + jc) * HID + 2 * p],
                       0.5f * w_hh[(1 * HID + jc) * HID + 2 * p + 1]);
    }
    u64 wxX2 = pack2(0.5f * w_ih[rX * HID + jc], 0.0f);
    u64 wxY2 = pack2(       w_ih[2 * HID + jc], 0.0f);
    u64 wxZ2 = pack2(0.5f * w_ih[1 * HID + jc], 0.0f);
    u64 bbX2 = pack2(0.5f * (b_ih[rX * HID + jc] + b_hh[rX * HID + jc]), 0.0f);
    u64 bbY2 = pack2(       (b_ih[2 * HID + jc] + b_hh[2 * HID + jc]), 0.0f);
    u64 bbZ2 = pack2(0.5f * (b_ih[1 * HID + jc] + b_hh[1 * HID + jc]), 0.0f);

    float cst = 0.0f;
    float hcst = 0.0f;                  // 0.5 * cst (A); don't-care in B
    bool isA = (half == 0);

    // Seed h = 0 in smem (half A owns the slots).
    if (isA) sts_f32(smy, 0.0f);
    __syncwarp();

    const float* xrow = x + (size_t)grp * LSEQ;

    // Load chunk 0 raw (12 floats) and compute its 4 conv outputs.
    float4 A4 = *reinterpret_cast<const float4*>(xrow);
    float4 M4 = *reinterpret_cast<const float4*>(xrow + 4);
    float4 C4 = *reinterpret_cast<const float4*>(xrow + 8);

    float cts[4];
    {
        float o0 = fmaf(A4.x, cw0, fmaf(A4.y, cw1, fmaf(A4.z, cw2, cb0)));
        float o1 = fmaf(A4.w, cw0, fmaf(M4.x, cw1, fmaf(M4.y, cw2, cb0)));
        float o2 = fmaf(M4.z, cw0, fmaf(M4.w, cw1, fmaf(C4.x, cw2, cb0)));
        float o3 = fmaf(C4.y, cw0, fmaf(C4.z, cw1, fmaf(C4.w, cw2, cb0)));
        cts[0] = fmaxf(o0, 0.0f);
        cts[1] = fmaxf(o1, 0.0f);
        cts[2] = fmaxf(o2, 0.0f);
        cts[3] = fmaxf(o3, 0.0f);
    }

    for (int t4 = 0; t4 < LP / 4; t4++) {
        // Prefetch next chunk's raw input (clamped on the last iteration).
        int nidx = t4 + 1 < LP / 4 ? t4 + 1 : t4;
        const float* np = xrow + 12 * nidx;
        A4 = *reinterpret_cast<const float4*>(np);
        M4 = *reinterpret_cast<const float4*>(np + 4);
        C4 = *reinterpret_cast<const float4*>(np + 8);

#pragma unroll
        for (int u = 0; u < 4; u++) {
            u64 ct2 = dup2(cts[u]);     // off critical path (ct known early)

            // Broadcast previous h as packed pairs (smem broadcast reads).
            u64 h01, h23, h45, h67, h89;
            lds_v2u64(sbase, h01, h23);
            lds_v2u64(sbase + 16u, h45, h67);
            h89 = lds_u64(sbase + 32u);

            // Seeds (independent of h; scheduled into the LDS shadow).
            u64 aX = ffma2(wxX2, ct2, bbX2);
            u64 aY = ffma2(wxY2, ct2, bbY2);
            u64 aZ = ffma2(wxZ2, ct2, bbZ2);

            // Three 5-deep FFMA2 chains, interleaved.
            aX = ffma2(wX2[0], h01, aX);
            aY = ffma2(wY2[0], h01, aY);
            aZ = ffma2(wZ2[0], h01, aZ);
            aX = ffma2(wX2[1], h23, aX);
            aY = ffma2(wY2[1], h23, aY);
            aZ = ffma2(wZ2[1], h23, aZ);
            aX = ffma2(wX2[2], h45, aX);
            aY = ffma2(wY2[2], h45, aY);
            aZ = ffma2(wZ2[2], h45, aZ);
            aX = ffma2(wX2[3], h67, aX);
            aY = ffma2(wY2[3], h67, aY);
            aZ = ffma2(wZ2[3], h67, aZ);
            aX = ffma2(wX2[4], h89, aX);
            aY = ffma2(wY2[4], h89, aY);
            aZ = ffma2(wZ2[4], h89, aZ);

            // tX = A: tanh(0.5*pre_i) | B: tanh(0.5*pre_o)
            float tX = tanh_apx(hsum2(aX));
            float tY = tanh_apx(hsum2(aY));   // A: tanh(pre_g)
            float tZ = tanh_apx(hsum2(aZ));   // A: tanh(0.5*pre_f)

            // B forms og = sig(o) = 0.5*tX + 0.5; shfl ships it to A early
            // (consumed only at the final h-mul -> latency hidden).
            float og_loc = fmaf(tX, 0.5f, 0.5f);
            float og = __shfl_xor_sync(0xffffffffu, og_loc, 16, 32);

            // c-update (valid in A; bounded don't-care in B):
            //   P = 0.5*gg*ti + 0.5*gg ; Q = 0.5*c + P ; c' = fma(0.5*c, tf, Q)
            float hgg = 0.5f * tY;
            float P = fmaf(hgg, tX, hgg);
            float Q = hcst + P;
            cst = fmaf(hcst, tZ, Q);
            hcst = 0.5f * cst;

            float h = og * tanh_apx(cst);

            // Publish new h for the next step (half A owns the slots).
            if (isA) sts_f32(smy, h);
        }

        // Conv for the prefetched chunk (identical expression order to the
        // reference conv -> bit-identical cts).
        {
            float o0 = fmaf(A4.x, cw0, fmaf(A4.y, cw1, fmaf(A4.z, cw2, cb0)));
            float o1 = fmaf(A4.w, cw0, fmaf(M4.x, cw1, fmaf(M4.y, cw2, cb0)));
            float o2 = fmaf(M4.z, cw0, fmaf(M4.w, cw1, fmaf(C4.x, cw2, cb0)));
            float o3 = fmaf(C4.y, cw0, fmaf(C4.z, cw1, fmaf(C4.w, cw2, cb0)));
            cts[0] = fmaxf(o0, 0.0f);
            cts[1] = fmaxf(o1, 0.0f);
            cts[2] = fmaxf(o2, 0.0f);
            cts[3] = fmaxf(o3, 0.0f);
        }
    }

    // Final MLP: read h_0..h_9 from smem; lanes 0..2 emit the 3 outputs.
    __syncwarp();
    if (lane < 3) {
        float h0, h1, h2, h3, h4, h5, h6, h7, h8, h9;
        lds_v2f(sbase,       h0, h1);
        lds_v2f(sbase + 8u,  h2, h3);
        lds_v2f(sbase + 16u, h4, h5);
        lds_v2f(sbase + 24u, h6, h7);
        lds_v2f(sbase + 32u, h8, h9);
        const float* mw = mlp_w + lane * HID;
        float acc = mlp_b[lane];
        acc = fmaf(mw[0], h0, acc);
        acc = fmaf(mw[1], h1, acc);
        acc = fmaf(mw[2], h2, acc);
        acc = fmaf(mw[3], h3, acc);
        acc = fmaf(mw[4], h4, acc);
        acc = fmaf(mw[5], h5, acc);
        acc = fmaf(mw[6], h6, acc);
        acc = fmaf(mw[7], h7, acc);
        acc = fmaf(mw[8], h8, acc);
        acc = fmaf(mw[9], h9, acc);
        out[grp * 3 + lane] = acc;
    }
}

// ---------------------------------------------------------------------------
extern "C" void kernel_launch(void* const* d_in, const int* in_sizes, int n_in,
                              void* d_out, int out_size) {
    const float* x      = (const float*)d_in[0];
    const float* conv_w = (const float*)d_in[1];
    const float* conv_b = (const float*)d_in[2];
    const float* w_ih   = (const float*)d_in[3];
    const float* w_hh   = (const float*)d_in[4];
    const float* b_ih   = (const float*)d_in[5];
    const float* b_hh   = (const float*)d_in[6];
    const float* mlp_w  = (const float*)d_in[7];
    const float* mlp_b  = (const float*)d_in[8];
    float* out = (float*)d_out;

    // Single fused kernel: 512 batches * 32 lanes = 16384 threads (128 x 128).
    int threads = 128;
    int blocks = (BATCH * 32) / threads;   // 128
    lstm_kernel<<<blocks, threads>>>(x, conv_w, conv_b, w_ih, w_hh,
                                     b_ih, b_hh, mlp_w, mlp_b, out);
}